// round 6
// baseline (speedup 1.0000x reference)
#include <cuda_runtime.h>

// Problem constants
#define Bq 4
#define Hq 16
#define Sq 4096
#define Dq 64
#define BHq (Bq*Hq)          // 64

#define SPLIT1 8
#define CHUNK1 (Sq/SPLIT1)   // 512 rows per pass-1 block
#define TILE1  16            // rows staged in smem per iteration

#define SPLIT3 16
#define CHUNK3 (Sq/SPLIT3)   // 256 rows per pass-3 block
#define SLAB   32            // rows per pass-3 inner slab (128 threads * 4s x 4e tiles / 64 e)

// Scratch (static device allocations are allowed; cudaMalloc is not)
__device__ float g_part[SPLIT1][BHq][Dq*Dq + Dq];  // partial kv + k_one, ~8.5 MB
__device__ float g_kv[BHq][Dq*Dq + Dq];            // reduced kv + k_one

typedef unsigned long long u64;

// packed fp32x2 FMA: d = a*b + d  (FFMA2 in SASS; 2x fp32 FMA throughput)
__device__ __forceinline__ void fma2(u64 &d, u64 a, u64 b) {
    asm("fma.rn.f32x2 %0, %1, %2, %0;" : "+l"(d) : "l"(a), "l"(b));
}
__device__ __forceinline__ float2 up2(u64 v) {
    float2 f;
    asm("mov.b64 {%0, %1}, %2;" : "=f"(f.x), "=f"(f.y) : "l"(v));
    return f;
}

// phi(x) = elu(x) + 1 = x+1 (x>0) else exp(x)
__device__ __forceinline__ float phif(float x) {
    return x > 0.f ? x + 1.f : __expf(x);
}

#define SCALE 0.3535533905932738f  // 1/sqrt(sqrt(64))

// ---------------------------------------------------------------------------
// Pass 1: per (bh, s-chunk) block computes partial kv[64][64] and k_one[64].
// 256 threads; each thread owns a 4(d) x 4(e) register tile, acc as 8 f32x2.
// phi(k) is stored DUPLICATED in smem (float2 (p,p)) so FFMA2 operands load
// directly via LDS.128 with no packing MOVs.
// ---------------------------------------------------------------------------
__global__ void __launch_bounds__(256)
k1_partial(const float* __restrict__ K, const float* __restrict__ V,
           const float* __restrict__ mask)
{
    __shared__ float2 ks2[TILE1][Dq];      // phi_k duplicated: 8 KB
    __shared__ float  vs [TILE1][Dq];      // v tile: 4 KB
    __shared__ float  k1buf[Dq][17];       // k_one partial reduce buffer

    const int t   = threadIdx.x;
    const int bh  = blockIdx.x & (BHq - 1);
    const int sp  = blockIdx.x >> 6;
    const int b   = bh / Hq;
    const int s0  = sp * CHUNK1;

    const int trow = t >> 4;               // staging row within tile (0..15)
    const int tcol = (t & 15) << 2;        // staging col (0..60)
    const int td4  = (t >> 4) << 2;        // accum d base
    const int te4  = (t & 15) << 2;        // accum e base

    u64 acc[4][2];
#pragma unroll
    for (int i = 0; i < 4; i++) { acc[i][0] = 0ull; acc[i][1] = 0ull; }
    float k1l[4] = {0.f, 0.f, 0.f, 0.f};

    const float* Kb = K + (size_t)bh * Sq * Dq;
    const float* Vb = V + (size_t)bh * Sq * Dq;
    const float* Mb = mask + (size_t)b * Sq;

    for (int it = 0; it < CHUNK1 / TILE1; it++) {
        const int srow = s0 + it * TILE1 + trow;
        // global loads issue before the barrier -> overlap previous accumulate
        const float4 kk = *(const float4*)(Kb + (size_t)srow * Dq + tcol);
        const float4 vv = *(const float4*)(Vb + (size_t)srow * Dq + tcol);
        const float  m  = Mb[srow];

        float p0 = phif(kk.x * SCALE) * m;
        float p1 = phif(kk.y * SCALE) * m;
        float p2 = phif(kk.z * SCALE) * m;
        float p3 = phif(kk.w * SCALE) * m;

        __syncthreads();   // previous tile fully consumed
        k1l[0] += p0; k1l[1] += p1; k1l[2] += p2; k1l[3] += p3;
        ks2[trow][tcol + 0] = make_float2(p0, p0);
        ks2[trow][tcol + 1] = make_float2(p1, p1);
        ks2[trow][tcol + 2] = make_float2(p2, p2);
        ks2[trow][tcol + 3] = make_float2(p3, p3);
        *(float4*)&vs[trow][tcol] = vv;
        __syncthreads();

#pragma unroll
        for (int r = 0; r < TILE1; r++) {
            const ulonglong2 vp = *(const ulonglong2*)&vs[r][te4];      // (v0,v1),(v2,v3)
            const ulonglong2 ka = *(const ulonglong2*)&ks2[r][td4];     // dup d0, d1
            const ulonglong2 kb = *(const ulonglong2*)&ks2[r][td4 + 2]; // dup d2, d3
            fma2(acc[0][0], ka.x, vp.x); fma2(acc[0][1], ka.x, vp.y);
            fma2(acc[1][0], ka.y, vp.x); fma2(acc[1][1], ka.y, vp.y);
            fma2(acc[2][0], kb.x, vp.x); fma2(acc[2][1], kb.x, vp.y);
            fma2(acc[3][0], kb.y, vp.x); fma2(acc[3][1], kb.y, vp.y);
        }
    }

    // write partial kv tile
    float* dst = &g_part[sp][bh][0];
#pragma unroll
    for (int i = 0; i < 4; i++) {
        const float2 a0 = up2(acc[i][0]);
        const float2 a1 = up2(acc[i][1]);
        *(float4*)&dst[(td4 + i) * Dq + te4] = make_float4(a0.x, a0.y, a1.x, a1.y);
    }

    // deterministic k_one reduction (no atomics)
    __syncthreads();
#pragma unroll
    for (int j = 0; j < 4; j++) k1buf[tcol + j][t >> 4] = k1l[j];
    __syncthreads();
    if (t < Dq) {
        float s = 0.f;
#pragma unroll
        for (int c = 0; c < 16; c++) s += k1buf[t][c];
        dst[Dq * Dq + t] = s;
    }
}

// ---------------------------------------------------------------------------
// Pass 2: reduce the SPLIT1 partials. Tiny.
// ---------------------------------------------------------------------------
__global__ void __launch_bounds__(256)
k2_reduce()
{
    const int bh = blockIdx.x;
    for (int idx = threadIdx.x; idx < Dq * Dq + Dq; idx += 256) {
        float s = 0.f;
#pragma unroll
        for (int sp = 0; sp < SPLIT1; sp++) s += g_part[sp][bh][idx];
        g_kv[bh][idx] = s;
    }
}

// ---------------------------------------------------------------------------
// Pass 3: out[s][e] = (phi_q[s] . kv[:,e]) / (phi_q[s] . k_one + 1e-8)
// 128 threads; SLAB=32 rows per inner pass; 4x4 register tiles, FFMA2.
// phi_q stored duplicated & row-padded (66 float2) -> conflict-free LDS.128.
// ---------------------------------------------------------------------------
__global__ void __launch_bounds__(128)
k3_out(const float* __restrict__ Q, const float* __restrict__ mask,
       float* __restrict__ out)
{
    __shared__ float2 qs2[SLAB][66];       // phi_q duplicated, padded: ~16.9 KB
    __shared__ float  kvs[Dq][Dq];         // 16 KB
    __shared__ float  k1s[Dq];
    __shared__ float  norms[SLAB];

    const int t  = threadIdx.x;
    const int bh = blockIdx.x >> 4;
    const int sp = blockIdx.x & 15;
    const int b  = bh / Hq;
    const int s0 = sp * CHUNK3;

    // load kv + k_one for this (b,h)
    for (int idx = t; idx < Dq * Dq; idx += 128) ((float*)kvs)[idx] = g_kv[bh][idx];
    if (t < Dq) k1s[t] = g_kv[bh][Dq * Dq + t];

    const float* Qb = Q + (size_t)bh * Sq * Dq;
    const float* Mb = mask + (size_t)b * Sq;
    float*       Ob = out + (size_t)bh * Sq * Dq;

    const int tcol = (t & 15) << 2;        // staging col
    const int ts4  = (t >> 4) << 2;        // s-row base within slab (0..28)
    const int te4  = (t & 15) << 2;        // e base

    for (int sl = 0; sl < CHUNK3 / SLAB; sl++) {
        const int sbase = s0 + sl * SLAB;

        // stage Q: 4 float4 per thread (gmem loads issued pre-barrier)
        float4 qv[4]; float mm[4];
#pragma unroll
        for (int k = 0; k < 4; k++) {
            const int row = (t >> 4) + k * 8;
            qv[k] = *(const float4*)(Qb + (size_t)(sbase + row) * Dq + tcol);
            mm[k] = Mb[sbase + row];
        }
        __syncthreads();  // A: previous slab (incl. norms reads) complete
#pragma unroll
        for (int k = 0; k < 4; k++) {
            const int row = (t >> 4) + k * 8;
            const float m = mm[k];
            qs2[row][tcol + 0] = make_float2(phif(qv[k].x * SCALE) * m, phif(qv[k].x * SCALE) * m);
            qs2[row][tcol + 1] = make_float2(phif(qv[k].y * SCALE) * m, phif(qv[k].y * SCALE) * m);
            qs2[row][tcol + 2] = make_float2(phif(qv[k].z * SCALE) * m, phif(qv[k].z * SCALE) * m);
            qs2[row][tcol + 3] = make_float2(phif(qv[k].w * SCALE) * m, phif(qv[k].w * SCALE) * m);
        }
        __syncthreads();  // B: qs2 (and on sl==0, kvs/k1s) ready

        u64 acc[4][2];
#pragma unroll
        for (int i = 0; i < 4; i++) { acc[i][0] = 0ull; acc[i][1] = 0ull; }

#pragma unroll 4
        for (int d = 0; d < Dq; d += 2) {
            const ulonglong2 bv0 = *(const ulonglong2*)&kvs[d][te4];
            const ulonglong2 bv1 = *(const ulonglong2*)&kvs[d + 1][te4];
#pragma unroll
            for (int i = 0; i < 4; i++) {
                const ulonglong2 av = *(const ulonglong2*)&qs2[ts4 + i][d]; // dup q_d, q_{d+1}
                fma2(acc[i][0], av.x, bv0.x); fma2(acc[i][1], av.x, bv0.y);
                fma2(acc[i][0], av.y, bv1.x); fma2(acc[i][1], av.y, bv1.y);
            }
        }

        // normalizer: 4 lanes per row, deterministic shfl reduce
        {
            const int s = t >> 2, quad = t & 3;
            float nsum = 0.f;
#pragma unroll
            for (int d = quad * 16; d < quad * 16 + 16; d++)
                nsum += qs2[s][d].x * k1s[d];
            nsum += __shfl_down_sync(0xffffffffu, nsum, 1);
            nsum += __shfl_down_sync(0xffffffffu, nsum, 2);
            if (quad == 0) norms[s] = nsum;
        }
        __syncthreads();  // C: norms visible; qs2 reads done

        // scale + write
#pragma unroll
        for (int i = 0; i < 4; i++) {
            const int s = ts4 + i;
            const float inv = 1.0f / (norms[s] + 1e-8f);
            const float2 a0 = up2(acc[i][0]);
            const float2 a1 = up2(acc[i][1]);
            *(float4*)(Ob + (size_t)(sbase + s) * Dq + te4) =
                make_float4(a0.x * inv, a0.y * inv, a1.x * inv, a1.y * inv);
        }
    }
}

// ---------------------------------------------------------------------------
extern "C" void kernel_launch(void* const* d_in, const int* in_sizes, int n_in,
                              void* d_out, int out_size)
{
    (void)in_sizes; (void)n_in; (void)out_size;
    const float* Q = (const float*)d_in[0];
    const float* K = (const float*)d_in[1];
    const float* V = (const float*)d_in[2];
    const float* M = (const float*)d_in[3];
    float* O = (float*)d_out;

    k1_partial<<<BHq * SPLIT1, 256>>>(K, V, M);
    k2_reduce <<<BHq,          256>>>();
    k3_out    <<<BHq * SPLIT3, 128>>>(Q, M, O);
}

// round 7
// speedup vs baseline: 1.0049x; 1.0049x over previous
#include <cuda_runtime.h>

#define Bq 4
#define Hq 16
#define Sq 4096
#define Dq 64
#define BHq (Bq*Hq)            // 64

#define SPLIT1 16
#define CHUNK1 (Sq/SPLIT1)     // 256 rows per pass-1 block
#define TILE1  32              // rows (16 s-pairs) staged per iteration
#define NPART  (SPLIT1*2)      // 2 s-subgroups write separate partials

#define SPLIT3 16
#define CHUNK3 (Sq/SPLIT3)     // 256 rows per pass-3 block
#define SLAB3  128             // rows per pass-3 inner slab

// static scratch (no cudaMalloc allowed)
__device__ float g_part[NPART][BHq][Dq*Dq];   // partial kv   (~34 MB)
__device__ float g_k1p [SPLIT1][BHq][Dq];     // partial k_one
__device__ float g_kv[BHq][Dq*Dq];
__device__ float g_k1[BHq][Dq];

typedef unsigned long long u64;

// packed fp32x2 FMA: d = a*b + d (FFMA2; 2x fp32 FMA throughput)
__device__ __forceinline__ void fma2(u64 &d, u64 a, u64 b) {
    asm("fma.rn.f32x2 %0, %1, %2, %0;" : "+l"(d) : "l"(a), "l"(b));
}
__device__ __forceinline__ float2 up2(u64 v) {
    float2 f;
    asm("mov.b64 {%0, %1}, %2;" : "=f"(f.x), "=f"(f.y) : "l"(v));
    return f;
}
__device__ __forceinline__ float phif(float x) {
    return x > 0.f ? x + 1.f : __expf(x);
}
#define SCALE 0.3535533905932738f  // 1/sqrt(sqrt(64))

// ---------------------------------------------------------------------------
// Pass 1: kv[d][e] partial sums, FFMA2 packed along the s axis (no dup).
// smem holds s-PAIRED tiles: ks2[p][d] = (phi_k[2p][d], phi_k[2p+1][d]).
// 256 threads = 2 s-subgroups x (16 d-thr x 8 e-thr), thread tile 4d x 8e.
// ---------------------------------------------------------------------------
__global__ void __launch_bounds__(256)
k1_partial(const float* __restrict__ K, const float* __restrict__ V,
           const float* __restrict__ mask)
{
    __shared__ __align__(16) float2 ks2[TILE1/2][Dq];  // 8 KB
    __shared__ __align__(16) float2 vs2[TILE1/2][Dq];  // 8 KB
    __shared__ float k1buf[Dq][17];

    const int t  = threadIdx.x;
    const int bh = blockIdx.x & (BHq - 1);
    const int sp = blockIdx.x >> 6;
    const int b  = bh >> 4;
    const int s0 = sp * CHUNK1;

    // staging role: each thread stages one s-pair x 4 d-cols of K and V
    const int p  = t >> 4;            // s-pair 0..15
    const int dg = (t & 15) << 2;     // col base 0..60
    // mma role
    const int grp   = t >> 7;         // s-subgroup 0/1
    const int tl    = t & 127;
    const int e_thr = tl & 7;         // e = e_thr + 8j
    const int d0    = (tl >> 3) << 2; // d base (16 d-threads x 4)

    u64 acc[4][8];
#pragma unroll
    for (int i = 0; i < 4; i++)
#pragma unroll
        for (int j = 0; j < 8; j++) acc[i][j] = 0ull;
    float2 k1a[4] = {{0.f,0.f},{0.f,0.f},{0.f,0.f},{0.f,0.f}};

    const float* Kb = K + (size_t)bh * Sq * Dq;
    const float* Vb = V + (size_t)bh * Sq * Dq;
    const float* Mb = mask + (size_t)b * Sq;

    for (int it = 0; it < CHUNK1 / TILE1; it++) {
        const int sa = s0 + it * TILE1 + 2 * p;
        // issue gmem loads before the barrier (overlap previous compute)
        const float4 ka = *(const float4*)(Kb + (size_t)sa * Dq + dg);
        const float4 kb = *(const float4*)(Kb + (size_t)(sa + 1) * Dq + dg);
        const float4 va = *(const float4*)(Vb + (size_t)sa * Dq + dg);
        const float4 vb = *(const float4*)(Vb + (size_t)(sa + 1) * Dq + dg);
        const float ma  = Mb[sa];
        const float mb2 = Mb[sa + 1];

        float2 P[4];
        P[0] = make_float2(phif(ka.x * SCALE) * ma, phif(kb.x * SCALE) * mb2);
        P[1] = make_float2(phif(ka.y * SCALE) * ma, phif(kb.y * SCALE) * mb2);
        P[2] = make_float2(phif(ka.z * SCALE) * ma, phif(kb.z * SCALE) * mb2);
        P[3] = make_float2(phif(ka.w * SCALE) * ma, phif(kb.w * SCALE) * mb2);

        __syncthreads();   // previous tile fully consumed
#pragma unroll
        for (int j = 0; j < 4; j++) {
            ks2[p][dg + j] = P[j];
            k1a[j].x += P[j].x; k1a[j].y += P[j].y;
        }
        vs2[p][dg + 0] = make_float2(va.x, vb.x);
        vs2[p][dg + 1] = make_float2(va.y, vb.y);
        vs2[p][dg + 2] = make_float2(va.z, vb.z);
        vs2[p][dg + 3] = make_float2(va.w, vb.w);
        __syncthreads();

#pragma unroll
        for (int s2g = 0; s2g < 8; s2g++) {
            const int s2 = 2 * s2g + grp;
            const ulonglong2 A01 = *(const ulonglong2*)&ks2[s2][d0];
            const ulonglong2 A23 = *(const ulonglong2*)&ks2[s2][d0 + 2];
            u64 B[8];
#pragma unroll
            for (int j = 0; j < 8; j++)
                B[j] = *(const u64*)&vs2[s2][e_thr + 8 * j];
#pragma unroll
            for (int j = 0; j < 8; j++) {
                fma2(acc[0][j], A01.x, B[j]);
                fma2(acc[1][j], A01.y, B[j]);
                fma2(acc[2][j], A23.x, B[j]);
                fma2(acc[3][j], A23.y, B[j]);
            }
        }
    }

    // write this subgroup's kv partial (horizontal add of the s-pair)
    float* dst = &g_part[sp * 2 + grp][bh][0];
#pragma unroll
    for (int i = 0; i < 4; i++)
#pragma unroll
        for (int j = 0; j < 8; j++) {
            const float2 v = up2(acc[i][j]);
            dst[(d0 + i) * Dq + e_thr + 8 * j] = v.x + v.y;
        }

    // deterministic k_one reduction
    __syncthreads();
#pragma unroll
    for (int j = 0; j < 4; j++) k1buf[dg + j][p] = k1a[j].x + k1a[j].y;
    __syncthreads();
    if (t < Dq) {
        float s = 0.f;
#pragma unroll
        for (int c = 0; c < 16; c++) s += k1buf[t][c];
        g_k1p[sp][bh][t] = s;
    }
}

// ---------------------------------------------------------------------------
// Pass 2: reduce the partials. 256 blocks for spread.
// ---------------------------------------------------------------------------
__global__ void __launch_bounds__(256)
k2_reduce()
{
    const int bh  = blockIdx.x >> 2;
    const int qtr = blockIdx.x & 3;
    const int base = qtr * (Dq * Dq / 4);
    for (int idx = threadIdx.x; idx < Dq * Dq / 4; idx += 256) {
        float s = 0.f;
#pragma unroll
        for (int p = 0; p < NPART; p++) s += g_part[p][bh][base + idx];
        g_kv[bh][base + idx] = s;
    }
    if (qtr == 0 && threadIdx.x < Dq) {
        float s = 0.f;
#pragma unroll
        for (int p = 0; p < SPLIT1; p++) s += g_k1p[p][bh][threadIdx.x];
        g_k1[bh][threadIdx.x] = s;
    }
}

// ---------------------------------------------------------------------------
// Pass 3: out = phi_q . kv / (phi_q . k_one + 1e-8), FFMA2 packed along d.
// phi_q stored PLAIN (natural d-pairs); kv re-paired once:
//   kvs2[d2][e] = (kv[2*d2][e], kv[2*d2+1][e]).
// 256 threads = 32 s-thr x 8 e-thr, thread tile 4s x 8e over a 128-row slab.
// ---------------------------------------------------------------------------
__global__ void __launch_bounds__(256)
k3_out(const float* __restrict__ Q, const float* __restrict__ mask,
       float* __restrict__ out)
{
    __shared__ float qs[SLAB3][68];                     // ~34.8 KB, pad 68
    __shared__ __align__(16) float2 kvs2[Dq/2][Dq];     // 16 KB
    __shared__ float k1s[Dq];
    __shared__ float norms[SLAB3];

    const int t  = threadIdx.x;
    const int bh = blockIdx.x >> 4;
    const int sp = blockIdx.x & 15;
    const int b  = bh >> 4;
    const int s0 = sp * CHUNK3;

    // prologue: load kv, build d-paired layout + k_one
    for (int idx = t; idx < Dq * Dq; idx += 256) {
        const int d = idx >> 6, e = idx & 63;
        ((float*)&kvs2[d >> 1][e])[d & 1] = g_kv[bh][idx];
    }
    if (t < Dq) k1s[t] = g_k1[bh][t];

    const float* Qb = Q + (size_t)bh * Sq * Dq;
    const float* Mb = mask + (size_t)b * Sq;
    float*       Ob = out + (size_t)bh * Sq * Dq;

    const int e_thr = t & 7;       // e = e_thr + 8j
    const int s_thr = t >> 3;      // rows s_thr + 32i
    const int r2 = t >> 1, hf = t & 1;   // staging: row r2, half hf

    for (int sl = 0; sl < CHUNK3 / SLAB3; sl++) {
        const int sbase = s0 + sl * SLAB3;

        __syncthreads();  // A: previous slab fully consumed (incl. norms)

        // stage phi_q: each thread does half a row (32 floats)
        {
            const float m = Mb[sbase + r2];
            const float* Qr = Qb + (size_t)(sbase + r2) * Dq + hf * 32;
#pragma unroll
            for (int c = 0; c < 8; c++) {
                const float4 q = *(const float4*)(Qr + 4 * c);
                float* dstq = &qs[r2][hf * 32 + 4 * c];
                dstq[0] = phif(q.x * SCALE) * m;
                dstq[1] = phif(q.y * SCALE) * m;
                dstq[2] = phif(q.z * SCALE) * m;
                dstq[3] = phif(q.w * SCALE) * m;
            }
        }
        __syncthreads();  // B: qs (and on sl==0, kvs2/k1s) ready

        u64 acc[4][8];
#pragma unroll
        for (int i = 0; i < 4; i++)
#pragma unroll
            for (int j = 0; j < 8; j++) acc[i][j] = 0ull;

#pragma unroll 8
        for (int dd = 0; dd < 16; dd++) {     // 4 d per iteration
            ulonglong2 A[4];
#pragma unroll
            for (int i = 0; i < 4; i++)
                A[i] = *(const ulonglong2*)&qs[s_thr + 32 * i][4 * dd];
            u64 B0[8], B1[8];
#pragma unroll
            for (int j = 0; j < 8; j++) {
                B0[j] = *(const u64*)&kvs2[2 * dd][e_thr + 8 * j];
                B1[j] = *(const u64*)&kvs2[2 * dd + 1][e_thr + 8 * j];
            }
#pragma unroll
            for (int i = 0; i < 4; i++)
#pragma unroll
                for (int j = 0; j < 8; j++) {
                    fma2(acc[i][j], A[i].x, B0[j]);
                    fma2(acc[i][j], A[i].y, B1[j]);
                }
        }

        // normalizer: 2 lanes per row, deterministic
        {
            float ns = 0.f;
#pragma unroll
            for (int d = hf * 32; d < hf * 32 + 32; d++)
                ns += qs[r2][d] * k1s[d];
            ns += __shfl_xor_sync(0xffffffffu, ns, 1);
            if (hf == 0) norms[r2] = ns;
        }
        __syncthreads();  // C: norms visible

#pragma unroll
        for (int i = 0; i < 4; i++) {
            const int s = s_thr + 32 * i;
            const float inv = 1.0f / (norms[s] + 1e-8f);
            float* Or = Ob + (size_t)(sbase + s) * Dq;
#pragma unroll
            for (int j = 0; j < 8; j++) {
                const float2 v = up2(acc[i][j]);
                Or[e_thr + 8 * j] = (v.x + v.y) * inv;
            }
        }
    }
}

// ---------------------------------------------------------------------------
extern "C" void kernel_launch(void* const* d_in, const int* in_sizes, int n_in,
                              void* d_out, int out_size)
{
    (void)in_sizes; (void)n_in; (void)out_size;
    const float* Q = (const float*)d_in[0];
    const float* K = (const float*)d_in[1];
    const float* V = (const float*)d_in[2];
    const float* M = (const float*)d_in[3];
    float* O = (float*)d_out;

    k1_partial<<<BHq * SPLIT1, 256>>>(K, V, M);
    k2_reduce <<<BHq * 4,      256>>>();
    k3_out    <<<BHq * SPLIT3, 256>>>(Q, M, O);
}

// round 8
// speedup vs baseline: 1.0120x; 1.0070x over previous
#include <cuda_runtime.h>

#define Bq 4
#define Hq 16
#define Sq 4096
#define Dq 64
#define BHq (Bq*Hq)            // 64

#define SPLIT1 16
#define CHUNK1 (Sq/SPLIT1)     // 256 rows per pass-1 block
#define TILE1  32              // rows (16 s-pairs) per staged tile
#define NIT1   (CHUNK1/TILE1)  // 8
#define NPART  (SPLIT1*2)

#define SPLIT3 16
#define CHUNK3 (Sq/SPLIT3)     // 256
#define SLAB3  64
#define NSL3   (CHUNK3/SLAB3)  // 4

__device__ float g_part[NPART][BHq][Dq*Dq];
__device__ float g_k1p [SPLIT1][BHq][Dq];
__device__ float g_kv[BHq][Dq*Dq];
__device__ float g_k1[BHq][Dq];

typedef unsigned long long u64;

__device__ __forceinline__ void fma2(u64 &d, u64 a, u64 b) {
    asm("fma.rn.f32x2 %0, %1, %2, %0;" : "+l"(d) : "l"(a), "l"(b));
}
__device__ __forceinline__ float2 up2(u64 v) {
    float2 f;
    asm("mov.b64 {%0, %1}, %2;" : "=f"(f.x), "=f"(f.y) : "l"(v));
    return f;
}
__device__ __forceinline__ float phif(float x) {
    return x > 0.f ? x + 1.f : __expf(x);
}
#define SCALE 0.3535533905932738f  // 1/sqrt(sqrt(64))

// ---------------------------------------------------------------------------
// Pass 1: kv[d][e] partials. FFMA2 packed along s (s-pairs), double-buffered
// smem, 1 barrier/tile, LDG(i+1) issued before compute(i).
// 256 thr = 2 s-subgroups x (16 d-thr x 8 e-thr); thread tile 4d x 16e(s-paired).
// ---------------------------------------------------------------------------
__global__ void __launch_bounds__(256)
k1_partial(const float* __restrict__ K, const float* __restrict__ V,
           const float* __restrict__ mask)
{
    __shared__ __align__(16) float2 ks2[2][TILE1/2][Dq];  // 16 KB
    __shared__ __align__(16) float2 vs2[2][TILE1/2][Dq];  // 16 KB
    __shared__ float k1buf[Dq][17];

    const int t  = threadIdx.x;
    const int bh = blockIdx.x & (BHq - 1);
    const int sp = blockIdx.x >> 6;
    const int b  = bh >> 4;
    const int s0 = sp * CHUNK1;

    const int p  = t >> 4;              // staged s-pair 0..15
    const int dg = (t & 15) << 2;       // staged col base
    const int grp   = t >> 7;           // s-subgroup
    const int tl    = t & 127;
    const int e_thr = tl & 7;
    const int d0    = (tl >> 3) << 2;

    u64 acc[4][8];
#pragma unroll
    for (int i = 0; i < 4; i++)
#pragma unroll
        for (int j = 0; j < 8; j++) acc[i][j] = 0ull;
    float2 k1a[4] = {{0.f,0.f},{0.f,0.f},{0.f,0.f},{0.f,0.f}};

    const float* Kb = K + (size_t)bh * Sq * Dq;
    const float* Vb = V + (size_t)bh * Sq * Dq;
    const float* Mb = mask + (size_t)b * Sq;

    float4 ka, kb, va, vb;
    float ma, mb2;

    // prologue: load + stage tile 0
    {
        const int sa = s0 + 2 * p;
        ka = *(const float4*)(Kb + (size_t)sa * Dq + dg);
        kb = *(const float4*)(Kb + (size_t)(sa + 1) * Dq + dg);
        va = *(const float4*)(Vb + (size_t)sa * Dq + dg);
        vb = *(const float4*)(Vb + (size_t)(sa + 1) * Dq + dg);
        ma = Mb[sa]; mb2 = Mb[sa + 1];
    }
    {
        float2 P0 = make_float2(phif(ka.x*SCALE)*ma, phif(kb.x*SCALE)*mb2);
        float2 P1 = make_float2(phif(ka.y*SCALE)*ma, phif(kb.y*SCALE)*mb2);
        float2 P2 = make_float2(phif(ka.z*SCALE)*ma, phif(kb.z*SCALE)*mb2);
        float2 P3 = make_float2(phif(ka.w*SCALE)*ma, phif(kb.w*SCALE)*mb2);
        k1a[0].x += P0.x; k1a[0].y += P0.y; k1a[1].x += P1.x; k1a[1].y += P1.y;
        k1a[2].x += P2.x; k1a[2].y += P2.y; k1a[3].x += P3.x; k1a[3].y += P3.y;
        *(float4*)&ks2[0][p][dg]     = make_float4(P0.x,P0.y,P1.x,P1.y);
        *(float4*)&ks2[0][p][dg + 2] = make_float4(P2.x,P2.y,P3.x,P3.y);
        *(float4*)&vs2[0][p][dg]     = make_float4(va.x,vb.x,va.y,vb.y);
        *(float4*)&vs2[0][p][dg + 2] = make_float4(va.z,vb.z,va.w,vb.w);
    }

#pragma unroll 1
    for (int it = 0; it < NIT1; it++) {
        __syncthreads();   // buf[it&1] ready; buf[(it+1)&1] free

        if (it + 1 < NIT1) {     // issue gmem loads for next tile
            const int sa = s0 + (it + 1) * TILE1 + 2 * p;
            ka = *(const float4*)(Kb + (size_t)sa * Dq + dg);
            kb = *(const float4*)(Kb + (size_t)(sa + 1) * Dq + dg);
            va = *(const float4*)(Vb + (size_t)sa * Dq + dg);
            vb = *(const float4*)(Vb + (size_t)(sa + 1) * Dq + dg);
            ma = Mb[sa]; mb2 = Mb[sa + 1];
        }

        const int bf = it & 1;
#pragma unroll
        for (int s2g = 0; s2g < 8; s2g++) {
            const int s2 = 2 * s2g + grp;
            const ulonglong2 A01 = *(const ulonglong2*)&ks2[bf][s2][d0];
            const ulonglong2 A23 = *(const ulonglong2*)&ks2[bf][s2][d0 + 2];
            ulonglong2 Bv[4];
#pragma unroll
            for (int jj = 0; jj < 4; jj++)
                Bv[jj] = *(const ulonglong2*)&vs2[bf][s2][2 * e_thr + 16 * jj];
#pragma unroll
            for (int jj = 0; jj < 4; jj++) {
                fma2(acc[0][2*jj],   A01.x, Bv[jj].x); fma2(acc[0][2*jj+1], A01.x, Bv[jj].y);
                fma2(acc[1][2*jj],   A01.y, Bv[jj].x); fma2(acc[1][2*jj+1], A01.y, Bv[jj].y);
                fma2(acc[2][2*jj],   A23.x, Bv[jj].x); fma2(acc[2][2*jj+1], A23.x, Bv[jj].y);
                fma2(acc[3][2*jj],   A23.y, Bv[jj].x); fma2(acc[3][2*jj+1], A23.y, Bv[jj].y);
            }
        }

        if (it + 1 < NIT1) {     // phi + stage next tile into other buffer
            const int nb = (it + 1) & 1;
            float2 P0 = make_float2(phif(ka.x*SCALE)*ma, phif(kb.x*SCALE)*mb2);
            float2 P1 = make_float2(phif(ka.y*SCALE)*ma, phif(kb.y*SCALE)*mb2);
            float2 P2 = make_float2(phif(ka.z*SCALE)*ma, phif(kb.z*SCALE)*mb2);
            float2 P3 = make_float2(phif(ka.w*SCALE)*ma, phif(kb.w*SCALE)*mb2);
            k1a[0].x += P0.x; k1a[0].y += P0.y; k1a[1].x += P1.x; k1a[1].y += P1.y;
            k1a[2].x += P2.x; k1a[2].y += P2.y; k1a[3].x += P3.x; k1a[3].y += P3.y;
            *(float4*)&ks2[nb][p][dg]     = make_float4(P0.x,P0.y,P1.x,P1.y);
            *(float4*)&ks2[nb][p][dg + 2] = make_float4(P2.x,P2.y,P3.x,P3.y);
            *(float4*)&vs2[nb][p][dg]     = make_float4(va.x,vb.x,va.y,vb.y);
            *(float4*)&vs2[nb][p][dg + 2] = make_float4(va.z,vb.z,va.w,vb.w);
        }
    }

    // kv partial epilogue (horizontal add of s-pair halves)
    float* dst = &g_part[sp * 2 + grp][bh][0];
#pragma unroll
    for (int i = 0; i < 4; i++)
#pragma unroll
        for (int jj = 0; jj < 4; jj++) {
            const float2 a = up2(acc[i][2*jj]);
            const float2 c = up2(acc[i][2*jj+1]);
            *(float2*)&dst[(d0 + i) * Dq + 2 * e_thr + 16 * jj] =
                make_float2(a.x + a.y, c.x + c.y);
        }

    // deterministic k_one reduction
#pragma unroll
    for (int j = 0; j < 4; j++) k1buf[dg + j][p] = k1a[j].x + k1a[j].y;
    __syncthreads();
    if (t < Dq) {
        float s = 0.f;
#pragma unroll
        for (int c = 0; c < 16; c++) s += k1buf[t][c];
        g_k1p[sp][bh][t] = s;
    }
}

// ---------------------------------------------------------------------------
// Pass 2: reduce partials.
// ---------------------------------------------------------------------------
__global__ void __launch_bounds__(256)
k2_reduce()
{
    const int bh  = blockIdx.x >> 2;
    const int qtr = blockIdx.x & 3;
    const int base = qtr * (Dq * Dq / 4);
    for (int idx = threadIdx.x; idx < Dq * Dq / 4; idx += 256) {
        float s = 0.f;
#pragma unroll
        for (int p = 0; p < NPART; p++) s += g_part[p][bh][base + idx];
        g_kv[bh][base + idx] = s;
    }
    if (qtr == 0 && threadIdx.x < Dq) {
        float s = 0.f;
#pragma unroll
        for (int p = 0; p < SPLIT1; p++) s += g_k1p[p][bh][threadIdx.x];
        g_k1[bh][threadIdx.x] = s;
    }
}

// ---------------------------------------------------------------------------
// Pass 3: out = phi_q.kv / (phi_q.k_one + 1e-8). FFMA2 packed along d.
// Double-buffered qs, 1 barrier/slab, LDG(sl+1) before compute(sl).
// Normalizer accumulated redundantly in-thread from A registers (no shfl,
// no norms smem, no extra barrier).
// 256 thr = 32 s-thr x 8 e-thr; thread tile 2s x 16e over 64-row slab.
// ---------------------------------------------------------------------------
__global__ void __launch_bounds__(256)
k3_out(const float* __restrict__ Q, const float* __restrict__ mask,
       float* __restrict__ out)
{
    __shared__ float qs[2][SLAB3][68];               // 34.8 KB
    __shared__ __align__(16) u64 kvs2[Dq/2][Dq];     // 16 KB, d-paired kv
    __shared__ __align__(16) u64 k1s2[Dq/2];         // d-paired k_one

    const int t  = threadIdx.x;
    const int bh = blockIdx.x >> 4;
    const int sp = blockIdx.x & 15;
    const int b  = bh >> 4;
    const int s0 = sp * CHUNK3;

    // prologue: build d-paired kv + k_one
    for (int idx = t; idx < Dq * Dq; idx += 256) {
        const int d = idx >> 6, e = idx & 63;
        ((float*)&kvs2[d >> 1][e])[d & 1] = g_kv[bh][idx];
    }
    if (t < Dq / 2) {
        ((float*)&k1s2[t])[0] = g_k1[bh][2 * t];
        ((float*)&k1s2[t])[1] = g_k1[bh][2 * t + 1];
    }

    const float* Qb = Q + (size_t)bh * Sq * Dq;
    const float* Mb = mask + (size_t)b * Sq;
    float*       Ob = out + (size_t)bh * Sq * Dq;

    const int r  = t >> 2;          // staging row 0..63
    const int qt = t & 3;           // staging quarter
    const int e_thr = t & 7;
    const int s_thr = t >> 3;       // rows s_thr, s_thr+32

    float4 qv[4]; float m;

    // prologue: load + stage slab 0
    {
        const int row = s0 + r;
        m = Mb[row];
        const float* Qr = Qb + (size_t)row * Dq + 16 * qt;
#pragma unroll
        for (int c = 0; c < 4; c++) qv[c] = *(const float4*)(Qr + 4 * c);
#pragma unroll
        for (int c = 0; c < 4; c++) {
            *(float4*)&qs[0][r][16 * qt + 4 * c] = make_float4(
                phif(qv[c].x*SCALE)*m, phif(qv[c].y*SCALE)*m,
                phif(qv[c].z*SCALE)*m, phif(qv[c].w*SCALE)*m);
        }
    }

#pragma unroll 1
    for (int sl = 0; sl < NSL3; sl++) {
        __syncthreads();   // qs[sl&1] + (sl==0) kvs2/k1s2 ready; other buf free

        if (sl + 1 < NSL3) {       // issue next slab's gmem loads
            const int row = s0 + (sl + 1) * SLAB3 + r;
            m = Mb[row];
            const float* Qr = Qb + (size_t)row * Dq + 16 * qt;
#pragma unroll
            for (int c = 0; c < 4; c++) qv[c] = *(const float4*)(Qr + 4 * c);
        }

        const int bf = sl & 1;
        u64 acc[2][8];
#pragma unroll
        for (int i = 0; i < 2; i++)
#pragma unroll
            for (int j = 0; j < 8; j++) acc[i][j] = 0ull;
        u64 n2[2] = {0ull, 0ull};

#pragma unroll
        for (int dd = 0; dd < 16; dd++) {
            const ulonglong2 A0 = *(const ulonglong2*)&qs[bf][s_thr][4 * dd];
            const ulonglong2 A1 = *(const ulonglong2*)&qs[bf][s_thr + 32][4 * dd];
            const ulonglong2 k12 = *(const ulonglong2*)&k1s2[2 * dd];
            ulonglong2 B0[4], B1[4];
#pragma unroll
            for (int jj = 0; jj < 4; jj++) {
                B0[jj] = *(const ulonglong2*)&kvs2[2 * dd][2 * e_thr + 16 * jj];
                B1[jj] = *(const ulonglong2*)&kvs2[2 * dd + 1][2 * e_thr + 16 * jj];
            }
#pragma unroll
            for (int jj = 0; jj < 4; jj++) {
                fma2(acc[0][2*jj],   A0.x, B0[jj].x); fma2(acc[0][2*jj+1], A0.x, B0[jj].y);
                fma2(acc[0][2*jj],   A0.y, B1[jj].x); fma2(acc[0][2*jj+1], A0.y, B1[jj].y);
                fma2(acc[1][2*jj],   A1.x, B0[jj].x); fma2(acc[1][2*jj+1], A1.x, B0[jj].y);
                fma2(acc[1][2*jj],   A1.y, B1[jj].x); fma2(acc[1][2*jj+1], A1.y, B1[jj].y);
            }
            fma2(n2[0], A0.x, k12.x); fma2(n2[0], A0.y, k12.y);
            fma2(n2[1], A1.x, k12.x); fma2(n2[1], A1.y, k12.y);
        }

        // epilogue: scale + write
        const int sbase = s0 + sl * SLAB3;
#pragma unroll
        for (int i = 0; i < 2; i++) {
            const int s = s_thr + 32 * i;
            const float2 nv = up2(n2[i]);
            const float inv = 1.0f / (nv.x + nv.y + 1e-8f);
            float* Or = Ob + (size_t)(sbase + s) * Dq;
#pragma unroll
            for (int jj = 0; jj < 4; jj++) {
                const float2 a = up2(acc[i][2*jj]);
                const float2 c = up2(acc[i][2*jj+1]);
                *(float2*)&Or[2 * e_thr + 16 * jj] =
                    make_float2((a.x + a.y) * inv, (c.x + c.y) * inv);
            }
        }

        if (sl + 1 < NSL3) {       // phi + stage next slab
            const int nb = (sl + 1) & 1;
#pragma unroll
            for (int c = 0; c < 4; c++) {
                *(float4*)&qs[nb][r][16 * qt + 4 * c] = make_float4(
                    phif(qv[c].x*SCALE)*m, phif(qv[c].y*SCALE)*m,
                    phif(qv[c].z*SCALE)*m, phif(qv[c].w*SCALE)*m);
            }
        }
    }
}

// ---------------------------------------------------------------------------
extern "C" void kernel_launch(void* const* d_in, const int* in_sizes, int n_in,
                              void* d_out, int out_size)
{
    (void)in_sizes; (void)n_in; (void)out_size;
    const float* Q = (const float*)d_in[0];
    const float* K = (const float*)d_in[1];
    const float* V = (const float*)d_in[2];
    const float* M = (const float*)d_in[3];
    float* O = (float*)d_out;

    k1_partial<<<BHq * SPLIT1, 256>>>(K, V, M);
    k2_reduce <<<BHq * 4,      256>>>();
    k3_out    <<<BHq * SPLIT3, 256>>>(Q, M, O);
}